// round 16
// baseline (speedup 1.0000x reference)
#include <cuda_runtime.h>
#include <cuda_fp16.h>
#include <math.h>
#include <stdint.h>

// ---------------- problem constants ----------------
#define NB    16
#define LSEQ  128
#define DH    768
#define MSP   8
#define HH    8
#define JR    30
#define RR    49
#define IMGD  2048
#define NM    128
#define UU    2048
#define NR    784
#define KP    448

typedef __half h16;

// ---------------- scratch ----------------
__device__ h16 g_enc[NR * IMGD];
__device__ h16 g_WalT[DH * IMGD];
__device__ h16 g_Wq[DH * HH * DH];
__device__ h16 g_Wk[DH * HH * DH];
__device__ h16 g_Wv[DH * HH * DH];
__device__ h16 g_WfcT[DH * HH * DH];
__device__ h16 g_C1[NR * DH];
__device__ h16 g_Bqk[HH * DH * DH];
__device__ h16 g_WvfT[HH * DH * DH];
__device__ h16 g_KC16[HH * NR * DH];
__device__ h16 g_VC16[HH * NR * DH];
__device__ h16 g_Pp[NB * LSEQ * KP];
__device__ h16 g_Vt[NB * DH * KP];
__device__ float g_attout[UU * DH];
__device__ h16 g_cat[UU * 2 * DH];
__device__ h16 g_Wa1T[2*DH * 2*DH];
__device__ h16 g_f1[UU * 2 * DH];
__device__ h16 g_Wa2T[DH * 2*DH];
__device__ h16 g_WdT[DH * DH];
__device__ float g_w2u[2*DH + 1];            // Wa2 @ W_un ; last = b_a2 . W_un
__device__ h16 g_pool16[NM * 2*DH];          // pooled f1 (128 x 1536)
__device__ h16 g_pf16[NM * DH];              // pooled @ Wa2 + b_a2 (fp16)
__device__ float g_hid[NM * DH];

// ---------------- helpers ----------------
__device__ __forceinline__ uint32_t smem_u32(const void* p) {
    uint32_t a;
    asm("{ .reg .u64 t; cvta.to.shared.u64 t, %1; cvt.u32.u64 %0, t; }" : "=r"(a) : "l"(p));
    return a;
}

__device__ __forceinline__ void ldm_x4(uint32_t* r, uint32_t addr) {
    asm volatile("ldmatrix.sync.aligned.m8n8.x4.shared.b16 {%0,%1,%2,%3}, [%4];"
                 : "=r"(r[0]), "=r"(r[1]), "=r"(r[2]), "=r"(r[3]) : "r"(addr));
}

__device__ __forceinline__ void mma16816(float* c, const uint32_t* a, uint32_t b0, uint32_t b1) {
    asm volatile(
        "mma.sync.aligned.m16n8k16.row.col.f32.f16.f16.f32 "
        "{%0,%1,%2,%3}, {%4,%5,%6,%7}, {%8,%9}, {%0,%1,%2,%3};"
        : "+f"(c[0]), "+f"(c[1]), "+f"(c[2]), "+f"(c[3])
        : "r"(a[0]), "r"(a[1]), "r"(a[2]), "r"(a[3]), "r"(b0), "r"(b1));
}

__device__ __forceinline__ void cpa16(uint32_t dst, const void* src) {
    asm volatile("cp.async.ca.shared.global [%0], [%1], 16;" :: "r"(dst), "l"(src));
}
__device__ __forceinline__ void cpa_commit() {
    asm volatile("cp.async.commit_group;" ::: "memory");
}
template<int N_>
__device__ __forceinline__ void cpa_wait() {
    asm volatile("cp.async.wait_group %0;" :: "n"(N_) : "memory");
}

// ---------------- fp16 tensor-core GEMM core v4 ----------------
#define BM 128
#define BN 128
#define BK 64
#define T_B 16384
#define STAGE_B 32768
#define MM_SMEM (2 * STAGE_B)

template<bool OUT_F16, bool TANH_ACT>
__device__ __forceinline__ void mm_body(
    const h16* __restrict__ A, int lda,
    const h16* __restrict__ B, int ldb,
    float* __restrict__ Cf, h16* __restrict__ Ch, int ldc,
    const float* __restrict__ bias, int M, int N, int K, int nst)
{
    extern __shared__ char dsm[];
    const uint32_t u_sm = smem_u32(dsm);

    const int tid = threadIdx.x, lane = tid & 31, wid = tid >> 5;
    const int wr = wid >> 1, wc = wid & 1;
    const int m0 = blockIdx.y * BM, n0 = blockIdx.x * BN;

    float acc[2][8][4];
#pragma unroll
    for (int i = 0; i < 2; i++)
#pragma unroll
        for (int j = 0; j < 8; j++)
#pragma unroll
            for (int e = 0; e < 4; e++) acc[i][j][e] = 0.f;

    const int lrow = lane & 15;
    const int khalf = lane >> 4;
    const int xk = lrow & 7;
    const uint32_t rA = (uint32_t)((wr * 32 + lrow) * 128);
    const uint32_t rB = (uint32_t)(T_B) + (uint32_t)((wc * 64 + lrow) * 128);

    auto load_stage = [&](int st, int k0) {
        const uint32_t sbase = u_sm + (uint32_t)(st * STAGE_B);
#pragma unroll
        for (int i = 0; i < 8; i++) {
            int u = tid + i * 256;
            int v = u & 1023;
            int r = v >> 3;
            int g = v & 7;
            const h16* src;
            uint32_t toff;
            if (u < 1024) { int ga = m0 + r; if (ga > M - 1) ga = M - 1;
                            src = A + (long)ga * lda + k0 + g * 8; toff = 0; }
            else          { int gb = n0 + r; if (gb > N - 1) gb = N - 1;
                            src = B + (long)gb * ldb + k0 + g * 8; toff = T_B; }
            uint32_t doff = toff + (uint32_t)(r * 128) + (uint32_t)(((g ^ (r & 7)) << 4));
            cpa16(sbase + doff, src);
        }
    };

    const int nch = K / BK;
    load_stage(0, 0);  cpa_commit();

    for (int ch = 0; ch < nch; ch++) {
        cpa_wait<0>();
        __syncthreads();
        if (ch + 1 < nch) {
            load_stage((ch + 1) & 1, (ch + 1) * BK);
            cpa_commit();
        }

        const uint32_t so = u_sm + (uint32_t)((ch & 1) * STAGE_B);
#pragma unroll
        for (int ks = 0; ks < 4; ks++) {
            const uint32_t sw = (uint32_t)((((ks * 2) | khalf) ^ xk) << 4);
            uint32_t bh[4][4];
#pragma unroll
            for (int nt = 0; nt < 4; nt++)
                ldm_x4(bh[nt], so + rB + (uint32_t)(nt * 2048) + sw);
#pragma unroll
            for (int mi = 0; mi < 2; mi++) {
                uint32_t ah[4];
                ldm_x4(ah, so + rA + (uint32_t)(mi * 2048) + sw);
#pragma unroll
                for (int nt = 0; nt < 4; nt++) {
#pragma unroll
                    for (int j = 0; j < 2; j++)
                        mma16816(acc[mi][nt * 2 + j], ah, bh[nt][j], bh[nt][j + 2]);
                }
            }
        }
    }

    const int er = m0 + wr * 32 + (lane >> 2);
    const int ec = n0 + wc * 64 + (lane & 3) * 2;
#pragma unroll
    for (int mi = 0; mi < 2; mi++) {
#pragma unroll
        for (int nj = 0; nj < 8; nj++) {
            const int col = ec + nj * 8;
            if (col >= nst) continue;
            float bv0 = 0.f, bv1 = 0.f;
            if (bias) { bv0 = bias[col]; bv1 = bias[col + 1]; }
#pragma unroll
            for (int half = 0; half < 2; half++) {
                const int row = er + mi * 16 + half * 8;
                if (row >= M) continue;
                float v0 = acc[mi][nj][half * 2 + 0] + bv0;
                float v1 = acc[mi][nj][half * 2 + 1] + bv1;
                if (TANH_ACT) { v0 = tanhf(v0); v1 = tanhf(v1); }
                const long base = (long)row * ldc + col;
                if (OUT_F16) {
                    __half2 h = __floats2half2_rn(v0, v1);
                    *reinterpret_cast<uint32_t*>(Ch + base) = reinterpret_cast<uint32_t&>(h);
                } else {
                    *reinterpret_cast<float2*>(Cf + base) = make_float2(v0, v1);
                }
            }
        }
    }
}

template<bool OUT_F16, bool TANH_ACT>
__global__ __launch_bounds__(256, 2)
void mmgemm(const h16* __restrict__ A, int lda, long sA,
            const h16* __restrict__ B, int ldb, long sB,
            float* __restrict__ Cf, h16* __restrict__ Ch,
            int ldc, long sC, const float* __restrict__ bias,
            int M, int N, int K, int nst)
{
    const long za = (long)blockIdx.z * sA, zb = (long)blockIdx.z * sB, zc = (long)blockIdx.z * sC;
    mm_body<OUT_F16, TANH_ACT>(
        A + za, lda, B + zb, ldb,
        Cf ? Cf + zc : nullptr, Ch ? Ch + zc : nullptr, ldc, bias, M, N, K, nst);
}

__global__ __launch_bounds__(256, 2)
void mm_g123(const h16* __restrict__ enc, const h16* __restrict__ walT,
             h16* __restrict__ c1, const float* __restrict__ b_align,
             const h16* __restrict__ wq, const h16* __restrict__ wk, h16* __restrict__ bqk,
             const h16* __restrict__ wfT, const h16* __restrict__ wv, h16* __restrict__ wvfT)
{
    int z = blockIdx.z;
    if (z == 0) {
        mm_body<true, false>(enc, IMGD, walT, IMGD, nullptr, c1, DH, b_align, NR, DH, IMGD, DH);
    } else {
        if (blockIdx.y * BM >= DH) return;
        z -= 1;
        const int set = z >> 3, h = z & 7;
        const long co = (long)h * DH;
        const long cc = (long)h * DH * DH;
        if (set == 0)
            mm_body<true, false>(wq + co, HH * DH, wk + co, HH * DH,
                                 nullptr, bqk + cc, DH, nullptr, DH, DH, DH, DH);
        else
            mm_body<true, false>(wfT + co, HH * DH, wv + co, HH * DH,
                                 nullptr, wvfT + cc, DH, nullptr, DH, DH, DH, DH);
    }
}

__global__ __launch_bounds__(256, 2)
void mm_g45(const h16* __restrict__ c1, const h16* __restrict__ bqk,
            const h16* __restrict__ wvfT, h16* __restrict__ kc, h16* __restrict__ vc)
{
    int z = blockIdx.z;
    const long NRD = (long)NR * DH;
    const long HD2 = (long)DH * DH;
    if (z < HH)
        mm_body<true, false>(c1, DH, bqk + (long)z * HD2, DH,
                             nullptr, kc + (long)z * NRD, DH, nullptr, NR, DH, DH, DH);
    else {
        z -= HH;
        mm_body<true, false>(c1, DH, wvfT + (long)z * HD2, DH,
                             nullptr, vc + (long)z * NRD, DH, nullptr, NR, DH, DH, DH);
    }
}

// ---------------- scores GEMM + fused softmax ----------------
__global__ __launch_bounds__(256, 2)
void mm_scores_softmax(const h16* __restrict__ cat, const h16* __restrict__ kc)
{
    extern __shared__ char dsm[];
    const uint32_t u_sm = smem_u32(dsm);
    const int z = blockIdx.z, n = z >> 3, hh = z & 7;
    const h16* A = cat + (long)n * LSEQ * 2 * DH;
    const h16* B = kc + ((long)hh * NR + (long)n * RR) * DH;
    const int lda = 2 * DH, ldb = DH;
    const int N = RR, K = DH;

    const int tid = threadIdx.x, lane = tid & 31, wid = tid >> 5;
    const int wr = wid >> 1, wc = wid & 1;

    float acc[2][8][4];
#pragma unroll
    for (int i = 0; i < 2; i++)
#pragma unroll
        for (int j = 0; j < 8; j++)
#pragma unroll
            for (int e = 0; e < 4; e++) acc[i][j][e] = 0.f;

    const int lrow = lane & 15;
    const int khalf = lane >> 4;
    const int xk = lrow & 7;
    const uint32_t rA = (uint32_t)((wr * 32 + lrow) * 128);
    const uint32_t rB = (uint32_t)(T_B) + (uint32_t)((wc * 64 + lrow) * 128);

    auto load_stage = [&](int st, int k0) {
        const uint32_t sbase = u_sm + (uint32_t)(st * STAGE_B);
#pragma unroll
        for (int i = 0; i < 8; i++) {
            int u = tid + i * 256;
            int v = u & 1023;
            int r = v >> 3;
            int g = v & 7;
            const h16* src;
            uint32_t toff;
            if (u < 1024) { src = A + (long)r * lda + k0 + g * 8; toff = 0; }
            else          { int gb = r; if (gb > N - 1) gb = N - 1;
                            src = B + (long)gb * ldb + k0 + g * 8; toff = T_B; }
            uint32_t doff = toff + (uint32_t)(r * 128) + (uint32_t)(((g ^ (r & 7)) << 4));
            cpa16(sbase + doff, src);
        }
    };

    const int nch = K / BK;
    load_stage(0, 0);  cpa_commit();

    for (int ch = 0; ch < nch; ch++) {
        cpa_wait<0>();
        __syncthreads();
        if (ch + 1 < nch) {
            load_stage((ch + 1) & 1, (ch + 1) * BK);
            cpa_commit();
        }
        const uint32_t so = u_sm + (uint32_t)((ch & 1) * STAGE_B);
#pragma unroll
        for (int ks = 0; ks < 4; ks++) {
            const uint32_t sw = (uint32_t)((((ks * 2) | khalf) ^ xk) << 4);
            uint32_t bh[4][4];
#pragma unroll
            for (int nt = 0; nt < 4; nt++)
                ldm_x4(bh[nt], so + rB + (uint32_t)(nt * 2048) + sw);
#pragma unroll
            for (int mi = 0; mi < 2; mi++) {
                uint32_t ah[4];
                ldm_x4(ah, so + rA + (uint32_t)(mi * 2048) + sw);
#pragma unroll
                for (int nt = 0; nt < 4; nt++) {
#pragma unroll
                    for (int j = 0; j < 2; j++)
                        mma16816(acc[mi][nt * 2 + j], ah, bh[nt][j], bh[nt][j + 2]);
                }
            }
        }
    }

    float* S = reinterpret_cast<float*>(dsm);
    __syncthreads();
    if (wc == 0) {
        const int er0 = wr * 32 + (lane >> 2);
        const int ec0 = (lane & 3) * 2;
#pragma unroll
        for (int mi = 0; mi < 2; mi++) {
#pragma unroll
            for (int nj = 0; nj < 8; nj++) {
                const int col = ec0 + nj * 8;
#pragma unroll
                for (int half = 0; half < 2; half++) {
                    const int row = er0 + mi * 16 + half * 8;
                    S[row * 65 + col]     = acc[mi][nj][half * 2 + 0];
                    S[row * 65 + col + 1] = acc[mi][nj][half * 2 + 1];
                }
            }
        }
    }
    __syncthreads();

    if (tid < 128) {
        const int t = tid;
        const float scale = rsqrtf((float)DH);
        float ex[RR];
        float mx = -1e30f;
#pragma unroll
        for (int r = 0; r < RR; r++) { float v = S[t * 65 + r] * scale; ex[r] = v; mx = fmaxf(mx, v); }
        float sum = 0.f;
#pragma unroll
        for (int r = 0; r < RR; r++) { float e = expf(ex[r] - mx); ex[r] = e; sum += e; }
        const float inv = 1.f / sum;
        h16* out = g_Pp + ((long)n * LSEQ + t) * KP + hh * RR;
#pragma unroll
        for (int r = 0; r < RR; r++) out[r] = __float2half(ex[r] * inv);
        if (hh == 0) {
            h16* pad = g_Pp + ((long)n * LSEQ + t) * KP + HH * RR;
            for (int i = 0; i < KP - HH * RR; i++) pad[i] = (h16)0.f;
        }
    }
}

// ---------------- VC fp16 -> Vt [n][d][h*49+r] ----------------
__global__ void transpose_v()
{
    __shared__ h16 tile[32][33];
    const int z = blockIdx.z, n = z >> 3, h = z & 7;
    const int d0 = blockIdx.x * 32, r0 = blockIdx.y * 32;
    const int tx = threadIdx.x, ty = threadIdx.y;
    for (int i = ty; i < 32; i += 8) {
        int r = r0 + i;
        h16 v = (h16)0.f;
        if (r < RR) v = g_VC16[((long)h * NR + (long)n * RR + r) * DH + d0 + tx];
        tile[i][tx] = v;
    }
    __syncthreads();
    for (int i = ty; i < 32; i += 8) {
        int r = r0 + tx;
        if (r < RR)
            g_Vt[((long)n * DH + d0 + i) * KP + h * RR + r] = tile[tx][i];
    }
}

// ---------------- residual + LN -> cat[:, 768:1536] fp16 ----------------
__global__ __launch_bounds__(256) void ln_cat(const float* __restrict__ seq,
                                              const float* __restrict__ gam,
                                              const float* __restrict__ bet)
{
    const int wid = threadIdx.x >> 5, lane = threadIdx.x & 31;
    for (int rr = 0; rr < 2; rr++) {
        const long u = (long)blockIdx.x * 16 + wid * 2 + rr;
        const float* ao = g_attout + u * DH;
        const float* sq = seq + u * DH;
        float s = 0.f;
        for (int k = lane; k < DH; k += 32) s += ao[k] + sq[k];
        for (int o = 16; o; o >>= 1) s += __shfl_xor_sync(0xffffffffu, s, o);
        float mu = s * (1.f / DH);
        float v = 0.f;
        for (int k = lane; k < DH; k += 32) { float d = ao[k] + sq[k] - mu; v += d * d; }
        for (int o = 16; o; o >>= 1) v += __shfl_xor_sync(0xffffffffu, v, o);
        float rstd = rsqrtf(v * (1.f / DH) + 1e-5f);
        h16* dst = g_cat + u * 2 * DH + DH;
        for (int k = lane * 2; k < DH; k += 64) {
            float a = (ao[k]     + sq[k]     - mu) * rstd * gam[k]     + bet[k];
            float b = (ao[k + 1] + sq[k + 1] - mu) * rstd * gam[k + 1] + bet[k + 1];
            __half2 h = __floats2half2_rn(a, b);
            *reinterpret_cast<uint32_t*>(dst + k) = reinterpret_cast<uint32_t&>(h);
        }
    }
}

// ---------------- merged straight conversions ----------------
#define N_ENC (NR * IMGD)
#define N_W   (DH * HH * DH)
__global__ void cvt_all(const float* __restrict__ enc_img, const float* __restrict__ Wq,
                        const float* __restrict__ Wk, const float* __restrict__ Wv)
{
    const long total = (long)N_ENC + 3L * N_W;
    long i0 = ((long)blockIdx.x * blockDim.x + threadIdx.x) * 8;
    long stride = (long)gridDim.x * blockDim.x * 8;
    for (long i = i0; i < total; i += stride) {
        const float* src; h16* dst; long off;
        if (i < N_ENC)                { src = enc_img; dst = g_enc; off = i; }
        else if (i < N_ENC + N_W)     { src = Wq; dst = g_Wq; off = i - N_ENC; }
        else if (i < N_ENC + 2L*N_W)  { src = Wk; dst = g_Wk; off = i - N_ENC - N_W; }
        else                          { src = Wv; dst = g_Wv; off = i - N_ENC - 2L*N_W; }
        float4 a = *reinterpret_cast<const float4*>(src + off);
        float4 b = *reinterpret_cast<const float4*>(src + off + 4);
        __half2 h0 = __floats2half2_rn(a.x, a.y);
        __half2 h1 = __floats2half2_rn(a.z, a.w);
        __half2 h2 = __floats2half2_rn(b.x, b.y);
        __half2 h3 = __floats2half2_rn(b.z, b.w);
        uint4 o;
        o.x = reinterpret_cast<uint32_t&>(h0);
        o.y = reinterpret_cast<uint32_t&>(h1);
        o.z = reinterpret_cast<uint32_t&>(h2);
        o.w = reinterpret_cast<uint32_t&>(h3);
        *reinterpret_cast<uint4*>(dst + off) = o;
    }
}

// ---------------- transposed conversions, early (W_align, Wfc) ----------------
__global__ void cvtT_early(const float* __restrict__ W_align, const float* __restrict__ Wfc)
{
    __shared__ float t[32][33];
    int b = blockIdx.x;
    const float* in; h16* out; int R, C, local;
    if (b < 1536) { in = W_align; out = g_WalT; R = 2048; C = 768; local = b; }
    else          { in = Wfc;     out = g_WfcT; R = 6144; C = 768; local = b - 1536; }
    const int tx = C / 32;
    const int cx = local % tx, ry = local / tx;
    const int c0 = cx * 32, r0 = ry * 32;
    for (int i = threadIdx.y; i < 32; i += 8)
        t[i][threadIdx.x] = in[(long)(r0 + i) * C + c0 + threadIdx.x];
    __syncthreads();
    if (threadIdx.x < 16) {
        for (int i = threadIdx.y; i < 32; i += 8) {
            __half2 h = __floats2half2_rn(t[2 * threadIdx.x][i], t[2 * threadIdx.x + 1][i]);
            long o = (long)(c0 + i) * R + r0 + 2 * threadIdx.x;
            *reinterpret_cast<uint32_t*>(out + o) = reinterpret_cast<uint32_t&>(h);
        }
    }
}

// ---------------- transposed conversions, late (W_a1, W_a2, W_dense) ----------------
__global__ void cvtT_late(const float* __restrict__ W_a1, const float* __restrict__ W_a2,
                          const float* __restrict__ W_dense)
{
    __shared__ float t[32][33];
    int b = blockIdx.x;
    const float* in; h16* out; int R, C, local;
    if (b < 2304)      { in = W_a1;    out = g_Wa1T; R = 1536; C = 1536; local = b; }
    else if (b < 3456) { in = W_a2;    out = g_Wa2T; R = 1536; C = 768;  local = b - 2304; }
    else               { in = W_dense; out = g_WdT;  R = 768;  C = 768;  local = b - 3456; }
    const int tx = C / 32;
    const int cx = local % tx, ry = local / tx;
    const int c0 = cx * 32, r0 = ry * 32;
    for (int i = threadIdx.y; i < 32; i += 8)
        t[i][threadIdx.x] = in[(long)(r0 + i) * C + c0 + threadIdx.x];
    __syncthreads();
    if (threadIdx.x < 16) {
        for (int i = threadIdx.y; i < 32; i += 8) {
            __half2 h = __floats2half2_rn(t[2 * threadIdx.x][i], t[2 * threadIdx.x + 1][i]);
            long o = (long)(c0 + i) * R + r0 + 2 * threadIdx.x;
            *reinterpret_cast<uint32_t*>(out + o) = reinterpret_cast<uint32_t&>(h);
        }
    }
}

// ---------------- seq -> cat[:, 0:768] fp16 ----------------
__global__ void seq_cvt_kernel(const float* __restrict__ seq)
{
    long i0 = ((long)blockIdx.x * blockDim.x + threadIdx.x) * 4;
    long stride = (long)gridDim.x * blockDim.x * 4;
    const long total = (long)UU * DH;
    for (long i = i0; i < total; i += stride) {
        long row = i / DH, col = i - row * DH;
        float4 v = *reinterpret_cast<const float4*>(seq + i);
        __half2 h0 = __floats2half2_rn(v.x, v.y);
        __half2 h1 = __floats2half2_rn(v.z, v.w);
        *reinterpret_cast<uint2*>(g_cat + row * 2 * DH + col) =
            make_uint2(reinterpret_cast<uint32_t&>(h0), reinterpret_cast<uint32_t&>(h1));
    }
}

// ---------------- w2u = Wa2 @ W_un ; b2u = b_a2 . W_un ----------------
__global__ void w2u_kernel(const float* __restrict__ W_a2, const float* __restrict__ W_un,
                           const float* __restrict__ b_a2)
{
    int k = blockIdx.x * 128 + threadIdx.x;        // 0..1535
    if (k < 2 * DH) {
        const float* row = W_a2 + (long)k * DH;    // W_a2 is [1536][768]
        float acc = 0.f;
        for (int d = 0; d < DH; d++) acc += row[d] * W_un[d];
        g_w2u[k] = acc;
    }
    if (blockIdx.x == 0 && threadIdx.x == 0) {
        float acc = 0.f;
        for (int d = 0; d < DH; d++) acc += b_a2[d] * W_un[d];
        g_w2u[2 * DH] = acc;
    }
}

// ---------------- pool over f1: scores from w2u, softmax, pooled 1536 fp16 ----------------
__global__ void pool2_kernel(const float* __restrict__ b_un,
                             const int* __restrict__ starts, const int* __restrict__ ends)
{
    int sp = blockIdx.x, t = threadIdx.x;
    int lane = t & 31, w = t >> 5;
    int n = sp >> 3;
    int base = n * LSEQ + starts[sp];
    __shared__ float sS[JR];
    __shared__ float sProb[JR];

    for (int j = w; j < JR; j += 8) {
        int u = base + j; if (u > UU - 1) u = UU - 1;
        const h16* fr = g_f1 + (long)u * 2 * DH;
        float acc = 0.f;
        for (int k = lane; k < 2 * DH; k += 32)
            acc += __half2float(fr[k]) * g_w2u[k];
        for (int o = 16; o; o >>= 1) acc += __shfl_xor_sync(0xffffffffu, acc, o);
        if (lane == 0) sS[j] = acc + g_w2u[2 * DH] + b_un[0];
    }
    __syncthreads();
    if (t == 0) {
        int width = ends[sp] - starts[sp] + 1;
        float mx = -1e30f;
        for (int j = 0; j < JR; j++) {
            float v = sS[j] + ((j < width) ? 0.f : -10000.f);
            sS[j] = v; mx = fmaxf(mx, v);
        }
        float sum = 0.f;
        for (int j = 0; j < JR; j++) { float e = expf(sS[j] - mx); sProb[j] = e; sum += e; }
        float inv = 1.f / sum;
        for (int j = 0; j < JR; j++) sProb[j] *= inv;
    }
    __syncthreads();
    for (int k = t; k < 2 * DH; k += 256) {
        float acc = 0.f;
        for (int j = 0; j < JR; j++) {
            int u = base + j; if (u > UU - 1) u = UU - 1;
            acc += sProb[j] * __half2float(g_f1[(long)u * 2 * DH + k]);
        }
        g_pool16[(long)sp * 2 * DH + k] = __float2half(acc);
    }
}

// ---------------- classifier ----------------
__global__ void cls_kernel(const float* __restrict__ W_cls, const float* __restrict__ b_cls,
                           float* __restrict__ out)
{
    int row = blockIdx.x, t = threadIdx.x;
    int lane = t & 31, c = t >> 5;
    const float* hr = g_hid + (long)row * DH;
    float acc = 0.f;
    for (int k = lane; k < DH; k += 32) acc += hr[k] * W_cls[k * 4 + c];
    for (int o = 16; o; o >>= 1) acc += __shfl_xor_sync(0xffffffffu, acc, o);
    if (lane == 0) out[row * 4 + c] = acc + b_cls[c];
}

// ---------------- launcher ----------------
extern "C" void kernel_launch(void* const* d_in, const int* in_sizes, int n_in,
                              void* d_out, int out_size)
{
    const float* enc_img  = (const float*)d_in[0];
    const float* seq      = (const float*)d_in[1];
    const int*   starts   = (const int*)d_in[3];
    const int*   ends     = (const int*)d_in[4];
    const float* W_align  = (const float*)d_in[5];
    const float* b_align  = (const float*)d_in[6];
    const float* Wq       = (const float*)d_in[7];
    const float* Wk       = (const float*)d_in[8];
    const float* Wv       = (const float*)d_in[9];
    const float* Wfc      = (const float*)d_in[10];
    const float* ln_g     = (const float*)d_in[11];
    const float* ln_b     = (const float*)d_in[12];
    const float* W_a1     = (const float*)d_in[13];
    const float* b_a1     = (const float*)d_in[14];
    const float* W_a2     = (const float*)d_in[15];
    const float* b_a2     = (const float*)d_in[16];
    const float* W_un     = (const float*)d_in[17];
    const float* b_un     = (const float*)d_in[18];
    const float* W_dense  = (const float*)d_in[19];
    const float* b_dense  = (const float*)d_in[20];
    const float* W_cls    = (const float*)d_in[21];
    const float* b_cls    = (const float*)d_in[22];

    h16 *enc, *walT, *wq, *wk, *wv, *wfT, *c1, *bqk, *wvfT, *kc, *vc, *cat, *wa1T, *f1, *wa2T;
    h16 *pp, *vt, *wdT, *pool16, *pf16;
    float *pAO, *pHid;
    cudaGetSymbolAddress((void**)&enc,  g_enc);
    cudaGetSymbolAddress((void**)&walT, g_WalT);
    cudaGetSymbolAddress((void**)&wq,   g_Wq);
    cudaGetSymbolAddress((void**)&wk,   g_Wk);
    cudaGetSymbolAddress((void**)&wv,   g_Wv);
    cudaGetSymbolAddress((void**)&wfT,  g_WfcT);
    cudaGetSymbolAddress((void**)&c1,   g_C1);
    cudaGetSymbolAddress((void**)&bqk,  g_Bqk);
    cudaGetSymbolAddress((void**)&wvfT, g_WvfT);
    cudaGetSymbolAddress((void**)&kc,   g_KC16);
    cudaGetSymbolAddress((void**)&vc,   g_VC16);
    cudaGetSymbolAddress((void**)&pp,   g_Pp);
    cudaGetSymbolAddress((void**)&vt,   g_Vt);
    cudaGetSymbolAddress((void**)&pAO,  g_attout);
    cudaGetSymbolAddress((void**)&cat,  g_cat);
    cudaGetSymbolAddress((void**)&wa1T, g_Wa1T);
    cudaGetSymbolAddress((void**)&f1,   g_f1);
    cudaGetSymbolAddress((void**)&wa2T, g_Wa2T);
    cudaGetSymbolAddress((void**)&wdT,  g_WdT);
    cudaGetSymbolAddress((void**)&pool16, g_pool16);
    cudaGetSymbolAddress((void**)&pf16, g_pf16);
    cudaGetSymbolAddress((void**)&pHid, g_hid);

    cudaFuncSetAttribute(mm_g123, cudaFuncAttributeMaxDynamicSharedMemorySize, MM_SMEM);
    cudaFuncSetAttribute(mm_g45,  cudaFuncAttributeMaxDynamicSharedMemorySize, MM_SMEM);
    cudaFuncSetAttribute(mm_scores_softmax, cudaFuncAttributeMaxDynamicSharedMemorySize, MM_SMEM);
    cudaFuncSetAttribute(mmgemm<true,  true >, cudaFuncAttributeMaxDynamicSharedMemorySize, MM_SMEM);
    cudaFuncSetAttribute(mmgemm<true,  false>, cudaFuncAttributeMaxDynamicSharedMemorySize, MM_SMEM);
    cudaFuncSetAttribute(mmgemm<false, false>, cudaFuncAttributeMaxDynamicSharedMemorySize, MM_SMEM);
    cudaFuncSetAttribute(mmgemm<false, true >, cudaFuncAttributeMaxDynamicSharedMemorySize, MM_SMEM);

    static cudaStream_t s1 = nullptr;
    static cudaEvent_t evRoot = nullptr, evEarly = nullptr, evLate = nullptr,
                       evG45 = nullptr, evTr = nullptr;
    if (s1 == nullptr) {
        cudaStreamCreateWithFlags(&s1, cudaStreamNonBlocking);
        cudaEventCreateWithFlags(&evRoot,  cudaEventDisableTiming);
        cudaEventCreateWithFlags(&evEarly, cudaEventDisableTiming);
        cudaEventCreateWithFlags(&evLate,  cudaEventDisableTiming);
        cudaEventCreateWithFlags(&evG45,   cudaEventDisableTiming);
        cudaEventCreateWithFlags(&evTr,    cudaEventDisableTiming);
    }

    const dim3 blk(256);

    // ---- fork ----
    cudaEventRecord(evRoot, 0);
    cudaStreamWaitEvent(s1, evRoot, 0);

    // ---- side: transposed conversions (early first), then the rest ----
    cvtT_early<<<6144, dim3(32, 8), 0, s1>>>(W_align, Wfc);
    cudaEventRecord(evEarly, s1);
    seq_cvt_kernel<<<1536, 256, 0, s1>>>(seq);
    cvtT_late<<<4032, dim3(32, 8), 0, s1>>>(W_a1, W_a2, W_dense);
    w2u_kernel<<<12, 128, 0, s1>>>(W_a2, W_un, b_a2);
    cudaEventRecord(evLate, s1);

    // ---- main: straight conversions concurrently, then big GEMMs ----
    cvt_all<<<2048, 256>>>(enc_img, Wq, Wk, Wv);
    cudaStreamWaitEvent(0, evEarly, 0);
    mm_g123<<<dim3(6, 7, 17), blk, MM_SMEM>>>(
        enc, walT, c1, b_align, wq, wk, bqk, wfT, wv, wvfT);
    mm_g45<<<dim3(6, 7, 16), blk, MM_SMEM>>>(c1, bqk, wvfT, kc, vc);
    cudaEventRecord(evG45, 0);

    // ---- side: V transpose after g45, concurrent with scores ----
    cudaStreamWaitEvent(s1, evG45, 0);
    transpose_v<<<dim3(DH / 32, 2, NB * HH), dim3(32, 8), 0, s1>>>();
    cudaEventRecord(evTr, s1);

    // ---- main: scores (needs seq half of cat) ----
    cudaStreamWaitEvent(0, evLate, 0);
    mm_scores_softmax<<<dim3(1, 1, NB * HH), blk, MM_SMEM>>>(cat, kc);

    // ---- main: attention out (needs Vt) ----
    cudaStreamWaitEvent(0, evTr, 0);
    mmgemm<false, false><<<dim3(6, 1, NB), blk, MM_SMEM>>>(
        pp, KP, (long)LSEQ * KP, vt, KP, (long)DH * KP,
        pAO, nullptr, DH, (long)LSEQ * DH, nullptr, LSEQ, DH, KP, DH);
    ln_cat<<<UU / 16, 256>>>(seq, ln_g, ln_b);

    // ---- fusion layer 1 only (Ga2 eliminated by pooling commutation) ----
    mmgemm<true, true><<<dim3(12, 16, 1), blk, MM_SMEM>>>(
        cat, 2 * DH, 0, wa1T, 2 * DH, 0,
        nullptr, f1, 2 * DH, 0, b_a1, UU, 2 * DH, 2 * DH, 2 * DH);

    // ---- pool f1 -> 1536, then two 128-row GEMMs + classifier ----
    pool2_kernel<<<NM, 256>>>(b_un, starts, ends);
    mmgemm<true, false><<<dim3(6, 1, 1), blk, MM_SMEM>>>(
        pool16, 2 * DH, 0, wa2T, 2 * DH, 0,
        nullptr, pf16, DH, 0, b_a2, NM, DH, 2 * DH, DH);
    mmgemm<false, true><<<dim3(6, 1, 1), blk, MM_SMEM>>>(
        pf16, DH, 0, wdT, DH, 0,
        pHid, nullptr, DH, 0, b_dense, NM, DH, DH, DH);
    cls_kernel<<<NM, 128>>>(W_cls, b_cls, (float*)d_out);
}